// round 2
// baseline (speedup 1.0000x reference)
#include <cuda_runtime.h>
#include <math.h>

#define SEQn 2048
#define Dn   768
#define Hn   8
#define DQKn 128
#define DVn  192
#define NQKVn 1344   /* 8*128 + 128 + 192 */
#define NPn  256
#define DPn  128
#define FFIn 1536
#define DPIn 256
#define EPS_RMS 1.1920929e-07f
#define EPS_LN  1e-5f

/* ---------------- scratch (device globals; no allocation) ---------------- */
__device__ float g_single[SEQn * Dn];
__device__ float g_pair[NPn * NPn * DPn];
__device__ float g_xn[SEQn * Dn];
__device__ float g_qkv[SEQn * NQKVn];
__device__ float g_q[Hn * SEQn * DQKn];
__device__ float g_k[SEQn * DQKn];
__device__ float g_v[SEQn * DVn];
__device__ float g_sim[(size_t)Hn * SEQn * SEQn];      /* 134 MB */
__device__ float g_pb[Hn * NPn * NPn];
__device__ float g_ao[SEQn * Hn * DVn];                /* 2048 x 1536 */
__device__ float g_t1[SEQn * FFIn];
__device__ float g_pxn[NPn * NPn * DPn];
__device__ float g_pqk[NPn * NPn * 2 * DPn];
__device__ float g_pv[NPn * NPn * DPn];
__device__ float g_psim[(size_t)NPn * NPn * NPn];      /* 67 MB */
__device__ float g_pt[NPn * NPn * DPIn];
__device__ float g_pt2[NPn * NPn * DPn];

/* ---------------- reductions ---------------- */
template <int OP>  /* 0 = sum, 1 = max */
__device__ __forceinline__ float blockReduce(float v) {
    __shared__ float s[33];
    int lane = threadIdx.x & 31, wid = threadIdx.x >> 5;
#pragma unroll
    for (int o = 16; o > 0; o >>= 1) {
        float ov = __shfl_down_sync(0xffffffffu, v, o);
        v = (OP == 0) ? (v + ov) : fmaxf(v, ov);
    }
    if (lane == 0) s[wid] = v;
    __syncthreads();
    if (threadIdx.x == 0) {
        int nw = (blockDim.x + 31) >> 5;
        float r = s[0];
        for (int i = 1; i < nw; i++) r = (OP == 0) ? (r + s[i]) : fmaxf(r, s[i]);
        s[32] = r;
    }
    __syncthreads();
    float r = s[32];
    __syncthreads();
    return r;
}

/* ---------------- generic tiled SGEMM: C = A @ B (or A @ B^T) ---------------- */
/* requires M%64==0, N%64==0, K%16==0 (all call sites satisfy this) */
template <bool TB>
__global__ __launch_bounds__(256) void gemm_kernel(
    int M, int N, int K,
    const float* __restrict__ A, int lda, long long sA,
    const float* __restrict__ B, int ldb, long long sB,
    float* __restrict__ C, int ldc, long long sC,
    const float* __restrict__ bias, int act)
{
    const int BM = 64, BN = 64, BK = 16;
    __shared__ float As[BK][BM];
    __shared__ float Bs[BK][BN];
    int batch = blockIdx.z;
    A += (long long)batch * sA;
    B += (long long)batch * sB;
    C += (long long)batch * sC;
    int bm = blockIdx.y * BM, bn = blockIdx.x * BN;
    int tid = threadIdx.x;
    int tr = tid / 16, tc = tid % 16;
    float acc[4][4];
#pragma unroll
    for (int i = 0; i < 4; i++)
#pragma unroll
        for (int j = 0; j < 4; j++) acc[i][j] = 0.f;

    for (int k0 = 0; k0 < K; k0 += BK) {
#pragma unroll
        for (int i = 0; i < 4; i++) {
            int idx = tid + i * 256;
            int mm = idx >> 4, kk = idx & 15;
            As[kk][mm] = A[(long long)(bm + mm) * lda + k0 + kk];
        }
        if (!TB) {
#pragma unroll
            for (int i = 0; i < 4; i++) {
                int idx = tid + i * 256;
                int kk = idx >> 6, nn = idx & 63;
                Bs[kk][nn] = B[(long long)(k0 + kk) * ldb + bn + nn];
            }
        } else {
#pragma unroll
            for (int i = 0; i < 4; i++) {
                int idx = tid + i * 256;
                int nn = idx >> 4, kk = idx & 15;
                Bs[kk][nn] = B[(long long)(bn + nn) * ldb + k0 + kk];
            }
        }
        __syncthreads();
#pragma unroll
        for (int kk = 0; kk < BK; kk++) {
            float a[4], b[4];
#pragma unroll
            for (int i = 0; i < 4; i++) a[i] = As[kk][tr * 4 + i];
#pragma unroll
            for (int j = 0; j < 4; j++) b[j] = Bs[kk][tc * 4 + j];
#pragma unroll
            for (int i = 0; i < 4; i++)
#pragma unroll
                for (int j = 0; j < 4; j++) acc[i][j] += a[i] * b[j];
        }
        __syncthreads();
    }
#pragma unroll
    for (int i = 0; i < 4; i++) {
        int m = bm + tr * 4 + i;
#pragma unroll
        for (int j = 0; j < 4; j++) {
            int n = bn + tc * 4 + j;
            float v = acc[i][j];
            if (bias) v += bias[n];
            if (act == 1) v = fmaxf(v, 0.f);
            C[(long long)m * ldc + n] = v;
        }
    }
}

/* ---------------- norms ---------------- */
__global__ void rmsnorm_k(const float* __restrict__ x, const float* __restrict__ w,
                          float* __restrict__ y, int cols)
{
    long long r = blockIdx.x;
    const float* xr = x + r * cols;
    float ss = 0.f;
    for (int c = threadIdx.x; c < cols; c += blockDim.x) { float v = xr[c]; ss += v * v; }
    ss = blockReduce<0>(ss);
    float inv = rsqrtf(ss / cols + EPS_RMS);
    for (int c = threadIdx.x; c < cols; c += blockDim.x)
        y[r * cols + c] = xr[c] * inv * w[c];
}

/* res[r,c] += rmsnorm(x[r,:]) * w  (in-place residual update) */
__global__ void rmsnorm_add_k(const float* __restrict__ x, const float* __restrict__ w,
                              float* __restrict__ res, int cols)
{
    long long r = blockIdx.x;
    const float* xr = x + r * cols;
    float ss = 0.f;
    for (int c = threadIdx.x; c < cols; c += blockDim.x) { float v = xr[c]; ss += v * v; }
    ss = blockReduce<0>(ss);
    float inv = rsqrtf(ss / cols + EPS_RMS);
    for (int c = threadIdx.x; c < cols; c += blockDim.x)
        res[r * cols + c] += xr[c] * inv * w[c];
}

__global__ void add_k(float* __restrict__ a, const float* __restrict__ b, long long n)
{
    long long i = (long long)blockIdx.x * blockDim.x + threadIdx.x;
    if (i < n) a[i] += b[i];
}

/* ---------------- qkv post: per-head LayerNorm + scale + rotary ---------------- */
/* grid (SEQ, 10): seg 0-7 = q heads, 8 = k, 9 = v. 192 threads. */
__global__ void qkv_post_k(const float* __restrict__ qkv,
                           const float* __restrict__ qn, const float* __restrict__ kn,
                           const float* __restrict__ vn,
                           float* __restrict__ q, float* __restrict__ k, float* __restrict__ v)
{
    int n = blockIdx.x, s = blockIdx.y, t = threadIdx.x;
    int len = (s == 9) ? 192 : 128;
    int off = (s < 8) ? s * 128 : (s == 8 ? 1024 : 1152);
    __shared__ float xs[192];
    float x = 0.f;
    if (t < len) x = qkv[(long long)n * NQKVn + off + t];
    float sum = blockReduce<0>(t < len ? x : 0.f);
    float sq  = blockReduce<0>(t < len ? x * x : 0.f);
    float mu = sum / len;
    float var = sq / len - mu * mu;
    float inv = rsqrtf(var + EPS_LN);
    float y = 0.f;
    if (t < len) {
        const float* w = (s < 8) ? qn : (s == 8 ? kn : vn);
        y = (x - mu) * inv * w[t];
        if (s < 8) y *= 0.125f;  /* SCALE = 64^-0.5 */
    }
    if (s == 9) { if (t < 192) v[n * DVn + t] = y; return; }
    /* rotary: inv_freq[d]=1/(d + 10^(1 + d*8128/63)); fp32 -> inf for d>=1 => only d=0 rotates */
    xs[t] = y;
    __syncthreads();
    if (t < 128) {
        int d2 = t & 63;
        float invf = (d2 == 0) ? 0.1f : 0.0f;
        float f = (float)n * invf;
        float c = cosf(f), si = sinf(f);
        float rh = (t < 64) ? -xs[t + 64] : xs[t - 64];
        float out = y * c + rh * si;
        if (s < 8) q[((size_t)s * SEQn + n) * DQKn + t] = out;
        else       k[n * DQKn + t] = out;
    }
}

/* ---------------- pairwise bias projection: rms -> gelu -> [128->8] ---------------- */
__global__ void pb_kernel(const float* __restrict__ pair, const float* __restrict__ rw,
                          const float* __restrict__ proj, float* __restrict__ pb)
{
    int ij = blockIdx.x, t = threadIdx.x;  /* 128 threads */
    float x = pair[(long long)ij * DPn + t];
    float ms = blockReduce<0>(x * x) * (1.f / DPn);
    float y = x * rsqrtf(ms + EPS_RMS) * rw[t];
    float g = 0.5f * y * (1.f + erff(y * 0.70710678118654752f));
    float p[8];
#pragma unroll
    for (int h = 0; h < 8; h++) p[h] = g * proj[t * 8 + h];
    __shared__ float sh[8][4];
    int lane = t & 31, wid = t >> 5;
#pragma unroll
    for (int h = 0; h < 8; h++) {
        float v = p[h];
        for (int o = 16; o > 0; o >>= 1) v += __shfl_down_sync(0xffffffffu, v, o);
        if (lane == 0) sh[h][wid] = v;
    }
    __syncthreads();
    if (t < 8) {
        float v = sh[t][0] + sh[t][1] + sh[t][2] + sh[t][3];
        int i = ij >> 8, j = ij & 255;
        pb[((t * NPn) + i) * NPn + j] = v;
    }
}

/* ---------------- softmax over sim rows with bias + softclamp ---------------- */
__global__ void softmax_sim_k(float* __restrict__ sim, const float* __restrict__ pb)
{
    int i = blockIdx.x, h = blockIdx.y, t = threadIdx.x;  /* 256 threads, 8 elems each */
    float* row = sim + ((size_t)h * SEQn + i) * SEQn;
    const float* pbr = pb + ((size_t)h * NPn + (i >> 3)) * NPn;
    float vals[8];
    float mx = -1e30f;
#pragma unroll
    for (int u = 0; u < 8; u++) {
        int j = t + u * 256;
        float x = row[j] + pbr[j >> 3];
        x = tanhf(x * 0.2f) * 5.f;
        vals[u] = x;
        mx = fmaxf(mx, x);
    }
    mx = blockReduce<1>(mx);
    float s = 0.f;
#pragma unroll
    for (int u = 0; u < 8; u++) { vals[u] = expf(vals[u] - mx); s += vals[u]; }
    s = blockReduce<0>(s);
    float r = 1.f / s;
#pragma unroll
    for (int u = 0; u < 8; u++) row[t + u * 256] = vals[u] * r;
}

/* ---------------- pairwise softmax (rows of 256) ---------------- */
__global__ void softmax_p_k(float* __restrict__ psim)
{
    long long r = blockIdx.x;
    float* row = psim + r * NPn;
    float x = row[threadIdx.x];
    float mx = blockReduce<1>(x);
    float e = expf(x - mx);
    float s = blockReduce<0>(e);
    row[threadIdx.x] = e / s;
}

/* ---------------- host helpers ---------------- */
static inline void launch_gemm(bool tb, int M, int N, int K,
                               const float* A, int lda, long long sA,
                               const float* B, int ldb, long long sB,
                               float* C, int ldc, long long sC, int batch,
                               const float* bias, int act)
{
    dim3 g(N / 64, M / 64, batch), b(256);
    if (tb) gemm_kernel<true ><<<g, b>>>(M, N, K, A, lda, sA, B, ldb, sB, C, ldc, sC, bias, act);
    else    gemm_kernel<false><<<g, b>>>(M, N, K, A, lda, sA, B, ldb, sB, C, ldc, sC, bias, act);
}

extern "C" void kernel_launch(void* const* d_in, const int* in_sizes, int n_in,
                              void* d_out, int out_size)
{
    (void)in_sizes; (void)n_in; (void)out_size;
    const float* in_single = (const float*)d_in[0];
    const float* in_pair   = (const float*)d_in[1];
    const float* W_attn_pre  = (const float*)d_in[2];
    const float* W_attn_post = (const float*)d_in[3];
    const float* W_qkv  = (const float*)d_in[4];
    const float* W_qn   = (const float*)d_in[5];
    const float* W_kn   = (const float*)d_in[6];
    const float* W_vn   = (const float*)d_in[7];
    const float* W_brms = (const float*)d_in[8];
    const float* W_bproj= (const float*)d_in[9];
    const float* W_out  = (const float*)d_in[10];
    const float* W_ffpre = (const float*)d_in[11];
    const float* W_ffpost= (const float*)d_in[12];
    const float* W_ff1  = (const float*)d_in[13];
    const float* B_ff1  = (const float*)d_in[14];
    const float* W_ff2  = (const float*)d_in[15];
    const float* B_ff2  = (const float*)d_in[16];
    const float* W_ppre = (const float*)d_in[17];
    const float* W_pqk  = (const float*)d_in[18];
    const float* W_pv   = (const float*)d_in[19];
    const float* B_pv   = (const float*)d_in[20];
    const float* W_pffpre = (const float*)d_in[21];
    const float* W_pff1 = (const float*)d_in[22];
    const float* B_pff1 = (const float*)d_in[23];
    const float* W_pff2 = (const float*)d_in[24];
    const float* B_pff2 = (const float*)d_in[25];

    float *single, *pair, *xn, *qkv, *q, *k, *v, *sim, *pb, *ao, *t1;
    float *pxn, *pqk, *pv, *psim, *pt, *pt2;
    cudaGetSymbolAddress((void**)&single, g_single);
    cudaGetSymbolAddress((void**)&pair, g_pair);
    cudaGetSymbolAddress((void**)&xn, g_xn);
    cudaGetSymbolAddress((void**)&qkv, g_qkv);
    cudaGetSymbolAddress((void**)&q, g_q);
    cudaGetSymbolAddress((void**)&k, g_k);
    cudaGetSymbolAddress((void**)&v, g_v);
    cudaGetSymbolAddress((void**)&sim, g_sim);
    cudaGetSymbolAddress((void**)&pb, g_pb);
    cudaGetSymbolAddress((void**)&ao, g_ao);
    cudaGetSymbolAddress((void**)&t1, g_t1);
    cudaGetSymbolAddress((void**)&pxn, g_pxn);
    cudaGetSymbolAddress((void**)&pqk, g_pqk);
    cudaGetSymbolAddress((void**)&pv, g_pv);
    cudaGetSymbolAddress((void**)&psim, g_psim);
    cudaGetSymbolAddress((void**)&pt, g_pt);
    cudaGetSymbolAddress((void**)&pt2, g_pt2);

    cudaMemcpyAsync(single, in_single, (size_t)SEQn * Dn * 4, cudaMemcpyDeviceToDevice);
    cudaMemcpyAsync(pair, in_pair, (size_t)NPn * NPn * DPn * 4, cudaMemcpyDeviceToDevice);

    for (int i = 0; i < 4; i++) {
        /* ---- single-track attention ---- */
        rmsnorm_k<<<SEQn, 256>>>(single, W_attn_pre + i * Dn, xn, Dn);
        launch_gemm(false, SEQn, NQKVn, Dn, xn, Dn, 0,
                    W_qkv + (long long)i * Dn * NQKVn, NQKVn, 0, qkv, NQKVn, 0, 1, nullptr, 0);
        qkv_post_k<<<dim3(SEQn, 10), 192>>>(qkv, W_qn + i * DQKn, W_kn + i * DQKn,
                                            W_vn + i * DVn, q, k, v);
        launch_gemm(true, SEQn, SEQn, DQKn, q, DQKn, (long long)SEQn * DQKn,
                    k, DQKn, 0, sim, SEQn, (long long)SEQn * SEQn, Hn, nullptr, 0);
        pb_kernel<<<NPn * NPn, 128>>>(pair, W_brms + i * DPn, W_bproj + i * DPn * Hn, pb);
        softmax_sim_k<<<dim3(SEQn, Hn), 256>>>(sim, pb);
        launch_gemm(false, SEQn, DVn, SEQn, sim, SEQn, (long long)SEQn * SEQn,
                    v, DVn, 0, ao, Hn * DVn, DVn, Hn, nullptr, 0);
        launch_gemm(false, SEQn, Dn, Hn * DVn, ao, Hn * DVn, 0,
                    W_out + (long long)i * Hn * DVn * Dn, Dn, 0, t1, Dn, 0, 1, nullptr, 0);
        rmsnorm_add_k<<<SEQn, 256>>>(t1, W_attn_post + i * Dn, single, Dn);

        /* ---- single-track FF ---- */
        rmsnorm_k<<<SEQn, 256>>>(single, W_ffpre + i * Dn, xn, Dn);
        launch_gemm(false, SEQn, FFIn, Dn, xn, Dn, 0,
                    W_ff1 + (long long)i * Dn * FFIn, FFIn, 0, ao, FFIn, 0, 1,
                    B_ff1 + i * FFIn, 1);
        launch_gemm(false, SEQn, Dn, FFIn, ao, FFIn, 0,
                    W_ff2 + (long long)i * FFIn * Dn, Dn, 0, t1, Dn, 0, 1,
                    B_ff2 + i * Dn, 0);
        rmsnorm_add_k<<<SEQn, 256>>>(t1, W_ffpost + i * Dn, single, Dn);

        /* ---- pairwise track (layers 0, 2) ---- */
        if ((i & 1) == 0) {
            int j = i / 2;
            rmsnorm_k<<<NPn * NPn, 128>>>(pair, W_ppre + j * DPn, pxn, DPn);
            launch_gemm(false, NPn * NPn, 2 * DPn, DPn, pxn, DPn, 0,
                        W_pqk + (long long)j * DPn * 2 * DPn, 2 * DPn, 0,
                        pqk, 2 * DPn, 0, 1, nullptr, 0);
            launch_gemm(false, NPn * NPn, DPn, DPn, pxn, DPn, 0,
                        W_pv + (long long)j * DPn * DPn, DPn, 0,
                        pv, DPn, 0, 1, B_pv + j * DPn, 0);
            launch_gemm(true, NPn, NPn, DPn, pqk, 2 * DPn, (long long)NPn * 2 * DPn,
                        pqk + DPn, 2 * DPn, (long long)NPn * 2 * DPn,
                        psim, NPn, (long long)NPn * NPn, NPn, nullptr, 0);
            softmax_p_k<<<NPn * NPn, NPn>>>(psim);
            launch_gemm(false, NPn, DPn, NPn, psim, NPn, (long long)NPn * NPn,
                        pv, DPn, (long long)NPn * DPn,
                        pt2, DPn, (long long)NPn * DPn, NPn, nullptr, 0);
            add_k<<<(NPn * NPn * DPn + 255) / 256, 256>>>(pair, pt2, (long long)NPn * NPn * DPn);
            rmsnorm_k<<<NPn * NPn, 128>>>(pair, W_pffpre + j * DPn, pxn, DPn);
            launch_gemm(false, NPn * NPn, DPIn, DPn, pxn, DPn, 0,
                        W_pff1 + (long long)j * DPn * DPIn, DPIn, 0,
                        pt, DPIn, 0, 1, B_pff1 + j * DPIn, 1);
            launch_gemm(false, NPn * NPn, DPn, DPIn, pt, DPIn, 0,
                        W_pff2 + (long long)j * DPIn * DPn, DPn, 0,
                        pt2, DPn, 0, 1, B_pff2 + j * DPn, 0);
            add_k<<<(NPn * NPn * DPn + 255) / 256, 256>>>(pair, pt2, (long long)NPn * NPn * DPn);
        }
    }

    /* outputs: single [2048*768] then pairwise [256*256*128] */
    cudaMemcpyAsync((float*)d_out, single, (size_t)SEQn * Dn * 4, cudaMemcpyDeviceToDevice);
    cudaMemcpyAsync((float*)d_out + SEQn * Dn, pair, (size_t)NPn * NPn * DPn * 4,
                    cudaMemcpyDeviceToDevice);
}

// round 3
// speedup vs baseline: 1.3328x; 1.3328x over previous
#include <cuda_runtime.h>
#include <math.h>

#define SEQn 2048
#define Dn   768
#define Hn   8
#define DQKn 128
#define DVn  192
#define NQKVn 1344   /* 8*128 + 128 + 192 */
#define NPn  256
#define DPn  128
#define FFIn 1536
#define DPIn 256
#define EPS_RMS 1.1920929e-07f
#define EPS_LN  1e-5f

/* ---------------- scratch (device globals; no allocation) ---------------- */
__device__ float g_single[SEQn * Dn];
__device__ float g_pair[NPn * NPn * DPn];
__device__ float g_xn[SEQn * Dn];
__device__ float g_qkv[SEQn * NQKVn];
__device__ float g_q[Hn * SEQn * DQKn];
__device__ float g_k[SEQn * DQKn];
__device__ float g_v[SEQn * DVn];
__device__ float g_sim[(size_t)Hn * SEQn * SEQn];      /* 134 MB */
__device__ float g_pb[Hn * NPn * NPn];
__device__ float g_ao[SEQn * Hn * DVn];                /* 2048 x 1536 */
__device__ float g_t1[SEQn * FFIn];
__device__ float g_pxn[NPn * NPn * DPn];
__device__ float g_pqk[NPn * NPn * 2 * DPn];
__device__ float g_pv[NPn * NPn * DPn];
__device__ float g_psim[(size_t)NPn * NPn * NPn];      /* 67 MB */
__device__ float g_pt[NPn * NPn * DPIn];
__device__ float g_pt2[NPn * NPn * DPn];

/* ---------------- reductions ---------------- */
template <int OP>  /* 0 = sum, 1 = max */
__device__ __forceinline__ float blockReduce(float v) {
    __shared__ float s[33];
    int lane = threadIdx.x & 31, wid = threadIdx.x >> 5;
#pragma unroll
    for (int o = 16; o > 0; o >>= 1) {
        float ov = __shfl_down_sync(0xffffffffu, v, o);
        v = (OP == 0) ? (v + ov) : fmaxf(v, ov);
    }
    if (lane == 0) s[wid] = v;
    __syncthreads();
    if (threadIdx.x == 0) {
        int nw = (blockDim.x + 31) >> 5;
        float r = s[0];
        for (int i = 1; i < nw; i++) r = (OP == 0) ? (r + s[i]) : fmaxf(r, s[i]);
        s[32] = r;
    }
    __syncthreads();
    float r = s[32];
    __syncthreads();
    return r;
}

/* ---------------- 128x128x8 double-buffered SGEMM: C = A@B (or A@B^T) -----
   requires M % 128 == 0, K % 8 == 0, N % 64 == 0 (guarded against tile OOB).
   A row-major [M,K]; B row-major [K,N] (TB=false) or [N,K] (TB=true).      */
template <bool TB>
__global__ __launch_bounds__(256) void gemm128_kernel(
    int M, int N, int K,
    const float* __restrict__ A, int lda, long long sA,
    const float* __restrict__ B, int ldb, long long sB,
    float* __restrict__ C, int ldc, long long sC,
    const float* __restrict__ bias, int act)
{
    __shared__ float As[2][8][128];
    __shared__ float Bs[2][8][128];
    int batch = blockIdx.z;
    A += (long long)batch * sA;
    B += (long long)batch * sB;
    C += (long long)batch * sC;
    const int bm = blockIdx.y * 128, bn = blockIdx.x * 128;
    const int tid = threadIdx.x;
    const int tx = tid & 15, ty = tid >> 4;

    /* A tile load mapping: 128 rows x 8 k, one float4 per thread */
    const int arow = tid >> 1, akq = (tid & 1) * 4;
    const float* Aptr = A + (long long)(bm + arow) * lda + akq;

    /* B tile load mapping */
    const int brow = tid >> 1, bkq = (tid & 1) * 4;   /* TB: n-row, k-quad  */
    const int bkr = tid >> 5, bnq = (tid & 31) * 4;   /* !TB: k-row, n-quad */
    const bool bvalid = TB ? (bn + brow < N) : (bn + bnq < N);
    const float4 f0 = make_float4(0.f, 0.f, 0.f, 0.f);

    float4 aReg, bReg;
    aReg = *(const float4*)(Aptr);
    if (TB)  bReg = bvalid ? *(const float4*)(B + (long long)(bn + brow) * ldb + bkq) : f0;
    else     bReg = bvalid ? *(const float4*)(B + (long long)bkr * ldb + bn + bnq)    : f0;

    As[0][akq + 0][arow] = aReg.x;
    As[0][akq + 1][arow] = aReg.y;
    As[0][akq + 2][arow] = aReg.z;
    As[0][akq + 3][arow] = aReg.w;
    if (TB) {
        Bs[0][bkq + 0][brow] = bReg.x;
        Bs[0][bkq + 1][brow] = bReg.y;
        Bs[0][bkq + 2][brow] = bReg.z;
        Bs[0][bkq + 3][brow] = bReg.w;
    } else {
        *(float4*)&Bs[0][bkr][bnq] = bReg;
    }
    __syncthreads();

    float acc[8][8];
#pragma unroll
    for (int i = 0; i < 8; i++)
#pragma unroll
        for (int j = 0; j < 8; j++) acc[i][j] = 0.f;

    const int nt = K >> 3;
    int buf = 0;
    for (int kt = 0; kt < nt; kt++) {
        if (kt + 1 < nt) {
            int k0 = (kt + 1) << 3;
            aReg = *(const float4*)(Aptr + k0);
            if (TB)  bReg = bvalid ? *(const float4*)(B + (long long)(bn + brow) * ldb + k0 + bkq) : f0;
            else     bReg = bvalid ? *(const float4*)(B + (long long)(k0 + bkr) * ldb + bn + bnq)  : f0;
        }
#pragma unroll
        for (int kk = 0; kk < 8; kk++) {
            float a[8], b[8];
            *(float4*)&a[0] = *(const float4*)&As[buf][kk][ty * 4];
            *(float4*)&a[4] = *(const float4*)&As[buf][kk][64 + ty * 4];
            *(float4*)&b[0] = *(const float4*)&Bs[buf][kk][tx * 4];
            *(float4*)&b[4] = *(const float4*)&Bs[buf][kk][64 + tx * 4];
#pragma unroll
            for (int i = 0; i < 8; i++)
#pragma unroll
                for (int j = 0; j < 8; j++) acc[i][j] = fmaf(a[i], b[j], acc[i][j]);
        }
        if (kt + 1 < nt) {
            buf ^= 1;
            As[buf][akq + 0][arow] = aReg.x;
            As[buf][akq + 1][arow] = aReg.y;
            As[buf][akq + 2][arow] = aReg.z;
            As[buf][akq + 3][arow] = aReg.w;
            if (TB) {
                Bs[buf][bkq + 0][brow] = bReg.x;
                Bs[buf][bkq + 1][brow] = bReg.y;
                Bs[buf][bkq + 2][brow] = bReg.z;
                Bs[buf][bkq + 3][brow] = bReg.w;
            } else {
                *(float4*)&Bs[buf][bkr][bnq] = bReg;
            }
        }
        __syncthreads();
    }

#pragma unroll
    for (int ih = 0; ih < 2; ih++) {
#pragma unroll
        for (int ii = 0; ii < 4; ii++) {
            int m = bm + ih * 64 + ty * 4 + ii;
#pragma unroll
            for (int jh = 0; jh < 2; jh++) {
                int n = bn + jh * 64 + tx * 4;
                if (n < N) {
                    float4 v;
                    v.x = acc[ih * 4 + ii][jh * 4 + 0];
                    v.y = acc[ih * 4 + ii][jh * 4 + 1];
                    v.z = acc[ih * 4 + ii][jh * 4 + 2];
                    v.w = acc[ih * 4 + ii][jh * 4 + 3];
                    if (bias) {
                        v.x += bias[n + 0]; v.y += bias[n + 1];
                        v.z += bias[n + 2]; v.w += bias[n + 3];
                    }
                    if (act == 1) {
                        v.x = fmaxf(v.x, 0.f); v.y = fmaxf(v.y, 0.f);
                        v.z = fmaxf(v.z, 0.f); v.w = fmaxf(v.w, 0.f);
                    }
                    *(float4*)&C[(long long)m * ldc + n] = v;
                }
            }
        }
    }
}

/* ---------------- norms ---------------- */
__global__ void rmsnorm_k(const float* __restrict__ x, const float* __restrict__ w,
                          float* __restrict__ y, int cols)
{
    long long r = blockIdx.x;
    const float* xr = x + r * cols;
    float ss = 0.f;
    for (int c = threadIdx.x; c < cols; c += blockDim.x) { float v = xr[c]; ss += v * v; }
    ss = blockReduce<0>(ss);
    float inv = rsqrtf(ss / cols + EPS_RMS);
    for (int c = threadIdx.x; c < cols; c += blockDim.x)
        y[r * cols + c] = xr[c] * inv * w[c];
}

/* res[r,c] += rmsnorm(x[r,:]) * w  (in-place residual update) */
__global__ void rmsnorm_add_k(const float* __restrict__ x, const float* __restrict__ w,
                              float* __restrict__ res, int cols)
{
    long long r = blockIdx.x;
    const float* xr = x + r * cols;
    float ss = 0.f;
    for (int c = threadIdx.x; c < cols; c += blockDim.x) { float v = xr[c]; ss += v * v; }
    ss = blockReduce<0>(ss);
    float inv = rsqrtf(ss / cols + EPS_RMS);
    for (int c = threadIdx.x; c < cols; c += blockDim.x)
        res[r * cols + c] += xr[c] * inv * w[c];
}

__global__ void add_k(float* __restrict__ a, const float* __restrict__ b, long long n)
{
    long long i = (long long)blockIdx.x * blockDim.x + threadIdx.x;
    if (i < n) a[i] += b[i];
}

/* ---------------- qkv post: per-head LayerNorm + scale + rotary ---------------- */
/* grid (SEQ, 10): seg 0-7 = q heads, 8 = k, 9 = v. 192 threads. */
__global__ void qkv_post_k(const float* __restrict__ qkv,
                           const float* __restrict__ qn, const float* __restrict__ kn,
                           const float* __restrict__ vn,
                           float* __restrict__ q, float* __restrict__ k, float* __restrict__ v)
{
    int n = blockIdx.x, s = blockIdx.y, t = threadIdx.x;
    int len = (s == 9) ? 192 : 128;
    int off = (s < 8) ? s * 128 : (s == 8 ? 1024 : 1152);
    __shared__ float xs[192];
    float x = 0.f;
    if (t < len) x = qkv[(long long)n * NQKVn + off + t];
    float sum = blockReduce<0>(t < len ? x : 0.f);
    float sq  = blockReduce<0>(t < len ? x * x : 0.f);
    float mu = sum / len;
    float var = sq / len - mu * mu;
    float inv = rsqrtf(var + EPS_LN);
    float y = 0.f;
    if (t < len) {
        const float* w = (s < 8) ? qn : (s == 8 ? kn : vn);
        y = (x - mu) * inv * w[t];
        if (s < 8) y *= 0.125f;  /* SCALE = 64^-0.5 */
    }
    if (s == 9) { if (t < 192) v[n * DVn + t] = y; return; }
    /* rotary: inv_freq[d]=1/(d + 10^(1 + d*8128/63)); fp32 -> inf for d>=1 => only d=0 rotates */
    xs[t] = y;
    __syncthreads();
    if (t < 128) {
        int d2 = t & 63;
        float invf = (d2 == 0) ? 0.1f : 0.0f;
        float f = (float)n * invf;
        float c = cosf(f), si = sinf(f);
        float rh = (t < 64) ? -xs[t + 64] : xs[t - 64];
        float out = y * c + rh * si;
        if (s < 8) q[((size_t)s * SEQn + n) * DQKn + t] = out;
        else       k[n * DQKn + t] = out;
    }
}

/* ---------------- pairwise bias projection: rms -> gelu -> [128->8] ---------------- */
__global__ void pb_kernel(const float* __restrict__ pair, const float* __restrict__ rw,
                          const float* __restrict__ proj, float* __restrict__ pb)
{
    int ij = blockIdx.x, t = threadIdx.x;  /* 128 threads */
    float x = pair[(long long)ij * DPn + t];
    float ms = blockReduce<0>(x * x) * (1.f / DPn);
    float y = x * rsqrtf(ms + EPS_RMS) * rw[t];
    float g = 0.5f * y * (1.f + erff(y * 0.70710678118654752f));
    float p[8];
#pragma unroll
    for (int h = 0; h < 8; h++) p[h] = g * proj[t * 8 + h];
    __shared__ float sh[8][4];
    int lane = t & 31, wid = t >> 5;
#pragma unroll
    for (int h = 0; h < 8; h++) {
        float v = p[h];
        for (int o = 16; o > 0; o >>= 1) v += __shfl_down_sync(0xffffffffu, v, o);
        if (lane == 0) sh[h][wid] = v;
    }
    __syncthreads();
    if (t < 8) {
        float v = sh[t][0] + sh[t][1] + sh[t][2] + sh[t][3];
        int i = ij >> 8, j = ij & 255;
        pb[((t * NPn) + i) * NPn + j] = v;
    }
}

/* ---------------- softmax over sim rows with bias + softclamp ---------------- */
__global__ void softmax_sim_k(float* __restrict__ sim, const float* __restrict__ pb)
{
    int i = blockIdx.x, h = blockIdx.y, t = threadIdx.x;  /* 256 threads, 8 elems each */
    float* row = sim + ((size_t)h * SEQn + i) * SEQn;
    const float* pbr = pb + ((size_t)h * NPn + (i >> 3)) * NPn;
    float vals[8];
    float mx = -1e30f;
#pragma unroll
    for (int u = 0; u < 8; u++) {
        int j = t + u * 256;
        float x = row[j] + pbr[j >> 3];
        x = tanhf(x * 0.2f) * 5.f;
        vals[u] = x;
        mx = fmaxf(mx, x);
    }
    mx = blockReduce<1>(mx);
    float s = 0.f;
#pragma unroll
    for (int u = 0; u < 8; u++) { vals[u] = expf(vals[u] - mx); s += vals[u]; }
    s = blockReduce<0>(s);
    float r = 1.f / s;
#pragma unroll
    for (int u = 0; u < 8; u++) row[t + u * 256] = vals[u] * r;
}

/* ---------------- pairwise softmax (rows of 256) ---------------- */
__global__ void softmax_p_k(float* __restrict__ psim)
{
    long long r = blockIdx.x;
    float* row = psim + r * NPn;
    float x = row[threadIdx.x];
    float mx = blockReduce<1>(x);
    float e = expf(x - mx);
    float s = blockReduce<0>(e);
    row[threadIdx.x] = e / s;
}

/* ---------------- host helpers ---------------- */
static inline void launch_gemm(bool tb, int M, int N, int K,
                               const float* A, int lda, long long sA,
                               const float* B, int ldb, long long sB,
                               float* C, int ldc, long long sC, int batch,
                               const float* bias, int act)
{
    dim3 g((N + 127) / 128, M / 128, batch), b(256);
    if (tb) gemm128_kernel<true ><<<g, b>>>(M, N, K, A, lda, sA, B, ldb, sB, C, ldc, sC, bias, act);
    else    gemm128_kernel<false><<<g, b>>>(M, N, K, A, lda, sA, B, ldb, sB, C, ldc, sC, bias, act);
}

extern "C" void kernel_launch(void* const* d_in, const int* in_sizes, int n_in,
                              void* d_out, int out_size)
{
    (void)in_sizes; (void)n_in; (void)out_size;
    const float* in_single = (const float*)d_in[0];
    const float* in_pair   = (const float*)d_in[1];
    const float* W_attn_pre  = (const float*)d_in[2];
    const float* W_attn_post = (const float*)d_in[3];
    const float* W_qkv  = (const float*)d_in[4];
    const float* W_qn   = (const float*)d_in[5];
    const float* W_kn   = (const float*)d_in[6];
    const float* W_vn   = (const float*)d_in[7];
    const float* W_brms = (const float*)d_in[8];
    const float* W_bproj= (const float*)d_in[9];
    const float* W_out  = (const float*)d_in[10];
    const float* W_ffpre = (const float*)d_in[11];
    const float* W_ffpost= (const float*)d_in[12];
    const float* W_ff1  = (const float*)d_in[13];
    const float* B_ff1  = (const float*)d_in[14];
    const float* W_ff2  = (const float*)d_in[15];
    const float* B_ff2  = (const float*)d_in[16];
    const float* W_ppre = (const float*)d_in[17];
    const float* W_pqk  = (const float*)d_in[18];
    const float* W_pv   = (const float*)d_in[19];
    const float* B_pv   = (const float*)d_in[20];
    const float* W_pffpre = (const float*)d_in[21];
    const float* W_pff1 = (const float*)d_in[22];
    const float* B_pff1 = (const float*)d_in[23];
    const float* W_pff2 = (const float*)d_in[24];
    const float* B_pff2 = (const float*)d_in[25];

    float *single, *pair, *xn, *qkv, *q, *k, *v, *sim, *pb, *ao, *t1;
    float *pxn, *pqk, *pv, *psim, *pt, *pt2;
    cudaGetSymbolAddress((void**)&single, g_single);
    cudaGetSymbolAddress((void**)&pair, g_pair);
    cudaGetSymbolAddress((void**)&xn, g_xn);
    cudaGetSymbolAddress((void**)&qkv, g_qkv);
    cudaGetSymbolAddress((void**)&q, g_q);
    cudaGetSymbolAddress((void**)&k, g_k);
    cudaGetSymbolAddress((void**)&v, g_v);
    cudaGetSymbolAddress((void**)&sim, g_sim);
    cudaGetSymbolAddress((void**)&pb, g_pb);
    cudaGetSymbolAddress((void**)&ao, g_ao);
    cudaGetSymbolAddress((void**)&t1, g_t1);
    cudaGetSymbolAddress((void**)&pxn, g_pxn);
    cudaGetSymbolAddress((void**)&pqk, g_pqk);
    cudaGetSymbolAddress((void**)&pv, g_pv);
    cudaGetSymbolAddress((void**)&psim, g_psim);
    cudaGetSymbolAddress((void**)&pt, g_pt);
    cudaGetSymbolAddress((void**)&pt2, g_pt2);

    cudaMemcpyAsync(single, in_single, (size_t)SEQn * Dn * 4, cudaMemcpyDeviceToDevice);
    cudaMemcpyAsync(pair, in_pair, (size_t)NPn * NPn * DPn * 4, cudaMemcpyDeviceToDevice);

    for (int i = 0; i < 4; i++) {
        /* ---- single-track attention ---- */
        rmsnorm_k<<<SEQn, 256>>>(single, W_attn_pre + i * Dn, xn, Dn);
        launch_gemm(false, SEQn, NQKVn, Dn, xn, Dn, 0,
                    W_qkv + (long long)i * Dn * NQKVn, NQKVn, 0, qkv, NQKVn, 0, 1, nullptr, 0);
        qkv_post_k<<<dim3(SEQn, 10), 192>>>(qkv, W_qn + i * DQKn, W_kn + i * DQKn,
                                            W_vn + i * DVn, q, k, v);
        launch_gemm(true, SEQn, SEQn, DQKn, q, DQKn, (long long)SEQn * DQKn,
                    k, DQKn, 0, sim, SEQn, (long long)SEQn * SEQn, Hn, nullptr, 0);
        pb_kernel<<<NPn * NPn, 128>>>(pair, W_brms + i * DPn, W_bproj + i * DPn * Hn, pb);
        softmax_sim_k<<<dim3(SEQn, Hn), 256>>>(sim, pb);
        launch_gemm(false, SEQn, DVn, SEQn, sim, SEQn, (long long)SEQn * SEQn,
                    v, DVn, 0, ao, Hn * DVn, DVn, Hn, nullptr, 0);
        launch_gemm(false, SEQn, Dn, Hn * DVn, ao, Hn * DVn, 0,
                    W_out + (long long)i * Hn * DVn * Dn, Dn, 0, t1, Dn, 0, 1, nullptr, 0);
        rmsnorm_add_k<<<SEQn, 256>>>(t1, W_attn_post + i * Dn, single, Dn);

        /* ---- single-track FF ---- */
        rmsnorm_k<<<SEQn, 256>>>(single, W_ffpre + i * Dn, xn, Dn);
        launch_gemm(false, SEQn, FFIn, Dn, xn, Dn, 0,
                    W_ff1 + (long long)i * Dn * FFIn, FFIn, 0, ao, FFIn, 0, 1,
                    B_ff1 + i * FFIn, 1);
        launch_gemm(false, SEQn, Dn, FFIn, ao, FFIn, 0,
                    W_ff2 + (long long)i * FFIn * Dn, Dn, 0, t1, Dn, 0, 1,
                    B_ff2 + i * Dn, 0);
        rmsnorm_add_k<<<SEQn, 256>>>(t1, W_ffpost + i * Dn, single, Dn);

        /* ---- pairwise track (layers 0, 2) ---- */
        if ((i & 1) == 0) {
            int j = i / 2;
            rmsnorm_k<<<NPn * NPn, 128>>>(pair, W_ppre + j * DPn, pxn, DPn);
            launch_gemm(false, NPn * NPn, 2 * DPn, DPn, pxn, DPn, 0,
                        W_pqk + (long long)j * DPn * 2 * DPn, 2 * DPn, 0,
                        pqk, 2 * DPn, 0, 1, nullptr, 0);
            launch_gemm(false, NPn * NPn, DPn, DPn, pxn, DPn, 0,
                        W_pv + (long long)j * DPn * DPn, DPn, 0,
                        pv, DPn, 0, 1, B_pv + j * DPn, 0);
            launch_gemm(true, NPn, NPn, DPn, pqk, 2 * DPn, (long long)NPn * 2 * DPn,
                        pqk + DPn, 2 * DPn, (long long)NPn * 2 * DPn,
                        psim, NPn, (long long)NPn * NPn, NPn, nullptr, 0);
            softmax_p_k<<<NPn * NPn, NPn>>>(psim);
            launch_gemm(false, NPn, DPn, NPn, psim, NPn, (long long)NPn * NPn,
                        pv, DPn, (long long)NPn * DPn,
                        pt2, DPn, (long long)NPn * DPn, NPn, nullptr, 0);
            add_k<<<(NPn * NPn * DPn + 255) / 256, 256>>>(pair, pt2, (long long)NPn * NPn * DPn);
            rmsnorm_k<<<NPn * NPn, 128>>>(pair, W_pffpre + j * DPn, pxn, DPn);
            launch_gemm(false, NPn * NPn, DPIn, DPn, pxn, DPn, 0,
                        W_pff1 + (long long)j * DPn * DPIn, DPIn, 0,
                        pt, DPIn, 0, 1, B_pff1 + j * DPIn, 1);
            launch_gemm(false, NPn * NPn, DPn, DPIn, pt, DPIn, 0,
                        W_pff2 + (long long)j * DPIn * DPn, DPn, 0,
                        pt2, DPn, 0, 1, B_pff2 + j * DPn, 0);
            add_k<<<(NPn * NPn * DPn + 255) / 256, 256>>>(pair, pt2, (long long)NPn * NPn * DPn);
        }
    }

    /* outputs: single [2048*768] then pairwise [256*256*128] */
    cudaMemcpyAsync((float*)d_out, single, (size_t)SEQn * Dn * 4, cudaMemcpyDeviceToDevice);
    cudaMemcpyAsync((float*)d_out + SEQn * Dn, pair, (size_t)NPn * NPn * DPn * 4,
                    cudaMemcpyDeviceToDevice);
}